// round 2
// baseline (speedup 1.0000x reference)
#include <cuda_runtime.h>
#include <cstdint>
#include <math.h>

// VectorQuantizer: N=262144 rows, D=256, K=1024 codes.
// out = [quantized_st (67108864 f32), loss, perplexity]
// Strategy: bit-exact replication of the XLA:CPU reference arithmetic:
//   a[n] = sequential fadd of fl(x_i^2), i ascending
//   b[k] = sequential fadd of fl(e_i^2), i ascending
//   c[n,k] = chained fma over k ascending (Eigen gebp order), single accumulator
//   d = fl(fl(a+b) - fl(2c)); argmin with lowest-index tie-break
//   out = fl(x + fl(q - x))

#define NROWS   262144
#define DIM     256
#define NCODES  1024
#define BM      128          // rows per CTA
#define BN      128          // codes per chunk
#define BD      64           // dims per smem stage
#define NTHR    256
#define NCHUNK  (NCODES / BN)   // 8
#define NDCH    (DIM / BD)      // 4
#define QELEMS  67108864

__device__ float  g_bsq[NCODES];
__device__ int    g_counts[NCODES];
__device__ double g_sqsum;

static __device__ __forceinline__ unsigned long long ffma2(unsigned long long a,
                                                           unsigned long long b,
                                                           unsigned long long c) {
    unsigned long long d;
    asm("fma.rn.f32x2 %0, %1, %2, %3;" : "=l"(d) : "l"(a), "l"(b), "l"(c));
    return d;
}
static __device__ __forceinline__ unsigned long long bcast2(float v) {
    unsigned long long r;
    asm("mov.b64 %0, {%1, %1};" : "=l"(r) : "f"(v));
    return r;
}
static __device__ __forceinline__ float2 unpack2(unsigned long long v) {
    float2 f;
    asm("mov.b64 {%0, %1}, %2;" : "=f"(f.x), "=f"(f.y) : "l"(v));
    return f;
}
// monotone float -> uint key (handles negatives); ties at equal bits preserved
static __device__ __forceinline__ unsigned int okey(float s) {
    unsigned int b = __float_as_uint(s);
    return (b & 0x80000000u) ? ~b : (b | 0x80000000u);
}
static __device__ __forceinline__ unsigned long long umin64(unsigned long long a,
                                                            unsigned long long b) {
    return a < b ? a : b;
}

// ---------------- init: counts=0, b[k] = strict sequential sum of squares ----------------
__global__ void vq_init_kernel(const float* __restrict__ cb) {
    int k = blockIdx.x * blockDim.x + threadIdx.x;
    if (k < NCODES) {
        g_counts[k] = 0;
        const float* r = cb + (size_t)k * DIM;
        float s = 0.f;
        for (int j = 0; j < DIM; ++j) {
            float v = r[j];
            s = __fadd_rn(s, __fmul_rn(v, v));   // strict: fl(s + fl(v*v)), ascending j
        }
        g_bsq[k] = s;
    }
    if (k == 0) g_sqsum = 0.0;
}

// ---------------- main: fused GEMM + rounded scoring + argmin + gather + MSE ----------------
__global__ __launch_bounds__(NTHR, 1)
void vq_main_kernel(const float* __restrict__ x, const float* __restrict__ cb,
                    float* __restrict__ out) {
    extern __shared__ float smem[];
    float* xs = smem;                 // [DIM][BM]   transposed x tile, 128 KB
    float* es = smem + DIM * BM;      // [BD][BN]    codebook stage, 32 KB (reused as scratch)
    float* sa = smem + DIM * BM + BD * BN;   // [BM] row sumsq a[n], 512 B

    const int tid = threadIdx.x;
    const int tx = tid & 15;          // code group
    const int ty = tid >> 4;          // row group
    const int r0 = ty * 8;
    const int c0 = tx * 8;
    const int m0 = blockIdx.x * BM;
    const float* xg = x + (size_t)m0 * DIM;

    // Load x tile, transposed: xs[d][row].
    for (int i = tid; i < BM * (DIM / 4); i += NTHR) {
        int row = i & (BM - 1);
        int dg  = i >> 7;             // 0..63
        float4 v = *(const float4*)(xg + (size_t)row * DIM + dg * 4);
        xs[(dg * 4 + 0) * BM + row] = v.x;
        xs[(dg * 4 + 1) * BM + row] = v.y;
        xs[(dg * 4 + 2) * BM + row] = v.z;
        xs[(dg * 4 + 3) * BM + row] = v.w;
    }
    __syncthreads();

    // a[n]: strict sequential sum of fl(x^2), d ascending (matches XLA fused reduce)
    if (tid < BM) {
        float aa = 0.f;
        for (int d = 0; d < DIM; ++d) {
            float v = xs[d * BM + tid];
            aa = __fadd_rn(aa, __fmul_rn(v, v));
        }
        sa[tid] = aa;
    }
    __syncthreads();

    float ar[8];
    #pragma unroll
    for (int r = 0; r < 8; ++r) ar[r] = sa[r0 + r];

    unsigned long long best[8];
    #pragma unroll
    for (int r = 0; r < 8; ++r) best[r] = 0xFFFFFFFFFFFFFFFFULL;

    for (int cch = 0; cch < NCHUNK; ++cch) {
        unsigned long long acc[8][4];  // [code][rowpair] packed f32x2, chained fma k=0..255
        #pragma unroll
        for (int c = 0; c < 8; ++c)
            #pragma unroll
            for (int p = 0; p < 4; ++p) acc[c][p] = 0ULL;

        for (int dch = 0; dch < NDCH; ++dch) {
            __syncthreads();
            // Stage codebook chunk transposed: es[d][code]
            for (int i = tid; i < BN * (BD / 4); i += NTHR) {
                int code = i & (BN - 1);
                int dg   = i >> 7;     // 0..15
                float4 v = *(const float4*)(cb + (size_t)(cch * BN + code) * DIM + dch * BD + dg * 4);
                es[(dg * 4 + 0) * BN + code] = v.x;
                es[(dg * 4 + 1) * BN + code] = v.y;
                es[(dg * 4 + 2) * BN + code] = v.z;
                es[(dg * 4 + 3) * BN + code] = v.w;
            }
            __syncthreads();

            const float* xbase = xs + dch * BD * BM + r0;
            const float* ebase = es + c0;
            #pragma unroll 8
            for (int dl = 0; dl < BD; ++dl) {   // k ascending: sequential fma chain per output
                ulonglong2 xa = *(const ulonglong2*)(xbase + dl * BM);      // rows r0..r0+3
                ulonglong2 xb = *(const ulonglong2*)(xbase + dl * BM + 4);  // rows r0+4..r0+7
                float4 e0 = *(const float4*)(ebase + dl * BN);
                float4 e1 = *(const float4*)(ebase + dl * BN + 4);
#define MMA8(cI, ev) { unsigned long long ee = bcast2(ev);       \
                acc[cI][0] = ffma2(xa.x, ee, acc[cI][0]);        \
                acc[cI][1] = ffma2(xa.y, ee, acc[cI][1]);        \
                acc[cI][2] = ffma2(xb.x, ee, acc[cI][2]);        \
                acc[cI][3] = ffma2(xb.y, ee, acc[cI][3]); }
                MMA8(0, e0.x) MMA8(1, e0.y) MMA8(2, e0.z) MMA8(3, e0.w)
                MMA8(4, e1.x) MMA8(5, e1.y) MMA8(6, e1.z) MMA8(7, e1.w)
#undef MMA8
            }
        }

        // chunk epilogue: d = fl(fl(a+b) - fl(2c)); running best (packed key|idx)
        #pragma unroll
        for (int c = 0; c < 8; ++c) {
            int cg = cch * BN + c0 + c;
            float b2 = g_bsq[cg];
            #pragma unroll
            for (int p = 0; p < 4; ++p) {
                float2 v = unpack2(acc[c][p]);
                float t0 = __fadd_rn(ar[2 * p],     b2);
                float t1 = __fadd_rn(ar[2 * p + 1], b2);
                float s0 = __fsub_rn(t0, __fmul_rn(2.0f, v.x));
                float s1 = __fsub_rn(t1, __fmul_rn(2.0f, v.y));
                unsigned long long p0 = ((unsigned long long)okey(s0) << 32) | (unsigned)cg;
                unsigned long long p1 = ((unsigned long long)okey(s1) << 32) | (unsigned)cg;
                best[2 * p]     = umin64(best[2 * p], p0);
                best[2 * p + 1] = umin64(best[2 * p + 1], p1);
            }
        }
    }

    // ---- cross-thread argmin reduction (reuse es region as scratch) ----
    __syncthreads();
    unsigned long long* red = (unsigned long long*)es;      // [BM][16] = 16 KB
    int*   sidx = (int*)(es + BM * 16 * 2);                 // +512 B
    float* red2 = (float*)(sidx + BM);                      // +1 KB

    #pragma unroll
    for (int r = 0; r < 8; ++r) red[(r0 + r) * 16 + tx] = best[r];
    __syncthreads();
    if (tid < BM) {
        unsigned long long b = red[tid * 16];
        #pragma unroll
        for (int j = 1; j < 16; ++j) b = umin64(b, red[tid * 16 + j]);
        int idx = (int)(b & 0xFFFFFFFFULL);
        sidx[tid] = idx;
        atomicAdd(&g_counts[idx], 1);
    }
    __syncthreads();

    // ---- fused straight-through output + MSE accumulation (coalesced) ----
    double sq = 0.0;
    float* og = out + (size_t)m0 * DIM;
    for (int i = tid; i < BM * DIM; i += NTHR) {
        int row = i >> 8;             // DIM == 256
        float e = cb[(size_t)sidx[row] * DIM + (i & 255)];
        float xv = xg[i];
        float df = __fsub_rn(e, xv);               // fl(q - x)
        og[i] = __fadd_rn(xv, df);                 // fl(x + fl(q - x))  (straight-through)
        float s2 = __fmul_rn(df, df);              // fl((q-x)^2)
        sq += (double)s2;
    }
    red2[tid] = (float)sq;   // fp32 partial fine for magnitude; keep fp64 path below
    // precise block reduction in double via shared (reuse red area)
    double* dred = (double*)red;
    dred[tid] = sq;
    __syncthreads();
    for (int s = NTHR / 2; s > 0; s >>= 1) {
        if (tid < s) dred[tid] += dred[tid + s];
        __syncthreads();
    }
    if (tid == 0) atomicAdd(&g_sqsum, dred[0]);
}

// ---------------- finalize: loss + perplexity (fp32 combine like reference) ----------------
__global__ void vq_final_kernel(float* __restrict__ out, long long out_size) {
    __shared__ float terms[NCODES];
    int t = threadIdx.x;
    // per-code entropy term in strict fp32: p*log(p + 1e-10)
    float p = __fdiv_rn((float)g_counts[t], (float)NROWS);
    terms[t] = __fmul_rn(p, logf(__fadd_rn(p, 1e-10f)));
    __syncthreads();
    if (t == 0 && out_size >= (long long)QELEMS + 2) {
        // sequential fp32 sum, k ascending (XLA reduce order)
        float s = 0.f;
        for (int k = 0; k < NCODES; ++k) s = __fadd_rn(s, terms[k]);
        // mean in fp32 from near-exact fp64 sum
        float m = (float)(g_sqsum / (double)QELEMS);
        // loss = q_latent + 0.25 * e_latent, both equal m: fl(m + fl(0.25*m))
        out[QELEMS]     = __fadd_rn(m, __fmul_rn(0.25f, m));
        out[QELEMS + 1] = expf(-s);
    }
}

extern "C" void kernel_launch(void* const* d_in, const int* in_sizes, int n_in,
                              void* d_out, int out_size) {
    const float* x  = (const float*)d_in[0];   // inputs  [8,32,32,32,256]
    const float* cb = (const float*)d_in[1];   // codebook [1024,256]
    float* out = (float*)d_out;

    const int smem_bytes = (DIM * BM + BD * BN + BM) * 4;   // 164352
    cudaFuncSetAttribute(vq_main_kernel,
                         cudaFuncAttributeMaxDynamicSharedMemorySize, smem_bytes);

    vq_init_kernel<<<(NCODES + 255) / 256, 256>>>(cb);
    vq_main_kernel<<<NROWS / BM, NTHR, smem_bytes>>>(x, cb, out);
    vq_final_kernel<<<1, NCODES>>>(out, (long long)out_size);
}

// round 5
// speedup vs baseline: 1.0829x; 1.0829x over previous
#include <cuda_runtime.h>
#include <cstdint>
#include <math.h>

// VectorQuantizer: N=262144 rows, D=256, K=1024 codes.
// out = [quantized_st (67108864 f32), loss, perplexity]
// Bit-exact replication of XLA:CPU reference arithmetic (validated R2):
//   a[n] = sequential fadd of fl(x_i^2), i ascending
//   b[k] = sequential fadd of fl(e_i^2), i ascending
//   c[n,k] = chained fp32 fma over k ascending, single accumulator
//   d = fl(fl(a+b) - fl(2c)); argmin, lowest-index tie-break
//   out = fl(x + fl(q - x))

#define NROWS   262144
#define DIM     256
#define NCODES  1024
#define BM      128             // rows per CTA
#define BN      256             // codes per chunk
#define BD      64              // dims per smem stage
#define NTHR    256
#define NCHUNK  (NCODES / BN)   // 4
#define NDCH    (DIM / BD)      // 4
#define QELEMS  67108864

__device__ float  g_bsq[NCODES];
__device__ int    g_counts[NCODES];
__device__ double g_sqsum;

static __device__ __forceinline__ unsigned long long ffma2(unsigned long long a,
                                                           unsigned long long b,
                                                           unsigned long long c) {
    unsigned long long d;
    asm("fma.rn.f32x2 %0, %1, %2, %3;" : "=l"(d) : "l"(a), "l"(b), "l"(c));
    return d;
}
static __device__ __forceinline__ unsigned long long bcast2(float v) {
    unsigned long long r;
    asm("mov.b64 %0, {%1, %1};" : "=l"(r) : "f"(v));
    return r;
}
static __device__ __forceinline__ float2 unpack2(unsigned long long v) {
    float2 f;
    asm("mov.b64 {%0, %1}, %2;" : "=f"(f.x), "=f"(f.y) : "l"(v));
    return f;
}
// monotone float -> uint key (handles negatives); equal bits preserve ties
static __device__ __forceinline__ unsigned int okey(float s) {
    unsigned int b = __float_as_uint(s);
    return (b & 0x80000000u) ? ~b : (b | 0x80000000u);
}
static __device__ __forceinline__ unsigned long long umin64(unsigned long long a,
                                                            unsigned long long b) {
    return a < b ? a : b;
}

// ---------------- init: one CTA per code; cooperative load, exact chain ----------------
__global__ void vq_init_kernel(const float* __restrict__ cb) {
    __shared__ float row[DIM];
    int k = blockIdx.x;
    int t = threadIdx.x;                 // 64 threads
    const float4* src = (const float4*)(cb + (size_t)k * DIM);
    float4 v = src[t];
    row[t * 4 + 0] = v.x; row[t * 4 + 1] = v.y;
    row[t * 4 + 2] = v.z; row[t * 4 + 3] = v.w;
    __syncthreads();
    if (t == 0) {
        float s = 0.f;
        #pragma unroll 8
        for (int j = 0; j < DIM; ++j) {
            float w = row[j];
            s = __fadd_rn(s, __fmul_rn(w, w));   // strict sequential, j ascending
        }
        g_bsq[k] = s;
        g_counts[k] = 0;
        if (k == 0) g_sqsum = 0.0;
    }
}

// ---------------- main: fused GEMM + rounded scoring + argmin + gather + MSE ----------------
__global__ __launch_bounds__(NTHR, 1)
void vq_main_kernel(const float* __restrict__ x, const float* __restrict__ cb,
                    float* __restrict__ out) {
    extern __shared__ float smem[];
    float* xs = smem;                         // [DIM][BM]  transposed x tile, 128 KB
    float* es = smem + DIM * BM;              // [BD][BN]   codebook stage, 64 KB (reused)
    float* sa = smem + DIM * BM + BD * BN;    // [BM] row sumsq

    const int tid = threadIdx.x;
    const int tx = tid & 31;                  // 32 code groups * 8 codes = 256
    const int ty = tid >> 5;                  // 8 row groups * 16 rows = 128
    const int r0 = ty * 16;
    const int c0 = tx * 8;
    const int m0 = blockIdx.x * BM;
    const float* xg = x + (size_t)m0 * DIM;

    // Load x tile transposed: xs[d][row]
    for (int i = tid; i < BM * (DIM / 4); i += NTHR) {
        int row = i & (BM - 1);
        int dg  = i >> 7;                     // 0..63
        float4 v = *(const float4*)(xg + (size_t)row * DIM + dg * 4);
        xs[(dg * 4 + 0) * BM + row] = v.x;
        xs[(dg * 4 + 1) * BM + row] = v.y;
        xs[(dg * 4 + 2) * BM + row] = v.z;
        xs[(dg * 4 + 3) * BM + row] = v.w;
    }
    __syncthreads();

    // a[n]: strict sequential sum of fl(x^2), d ascending
    if (tid < BM) {
        float aa = 0.f;
        for (int d = 0; d < DIM; ++d) {
            float v = xs[d * BM + tid];
            aa = __fadd_rn(aa, __fmul_rn(v, v));
        }
        sa[tid] = aa;
    }
    __syncthreads();

    float ar[16];
    #pragma unroll
    for (int r = 0; r < 16; ++r) ar[r] = sa[r0 + r];

    unsigned long long best[16];
    #pragma unroll
    for (int r = 0; r < 16; ++r) best[r] = 0xFFFFFFFFFFFFFFFFULL;

    for (int cch = 0; cch < NCHUNK; ++cch) {
        unsigned long long acc[8][8];         // [code][rowpair], chained fma k ascending
        #pragma unroll
        for (int c = 0; c < 8; ++c)
            #pragma unroll
            for (int p = 0; p < 8; ++p) acc[c][p] = 0ULL;

        for (int dch = 0; dch < NDCH; ++dch) {
            __syncthreads();
            // Stage codebook chunk transposed: es[d][code]
            for (int i = tid; i < BN * (BD / 4); i += NTHR) {
                int code = i & (BN - 1);
                int dg   = i >> 8;            // 0..15
                float4 v = *(const float4*)(cb + (size_t)(cch * BN + code) * DIM + dch * BD + dg * 4);
                es[(dg * 4 + 0) * BN + code] = v.x;
                es[(dg * 4 + 1) * BN + code] = v.y;
                es[(dg * 4 + 2) * BN + code] = v.z;
                es[(dg * 4 + 3) * BN + code] = v.w;
            }
            __syncthreads();

            const float* xbase = xs + dch * BD * BM + r0;
            const float* ebase = es + c0;
            #pragma unroll 4
            for (int dl = 0; dl < BD; ++dl) { // k ascending: per-output sequential fma chain
                ulonglong2 xa = *(const ulonglong2*)(xbase + dl * BM);       // rows +0..3
                ulonglong2 xb = *(const ulonglong2*)(xbase + dl * BM + 4);   // rows +4..7
                ulonglong2 xc = *(const ulonglong2*)(xbase + dl * BM + 8);   // rows +8..11
                ulonglong2 xd = *(const ulonglong2*)(xbase + dl * BM + 12);  // rows +12..15
                float4 e0 = *(const float4*)(ebase + dl * BN);
                float4 e1 = *(const float4*)(ebase + dl * BN + 4);
#define MMA16(cI, ev) { unsigned long long ee = bcast2(ev);      \
                acc[cI][0] = ffma2(xa.x, ee, acc[cI][0]);        \
                acc[cI][1] = ffma2(xa.y, ee, acc[cI][1]);        \
                acc[cI][2] = ffma2(xb.x, ee, acc[cI][2]);        \
                acc[cI][3] = ffma2(xb.y, ee, acc[cI][3]);        \
                acc[cI][4] = ffma2(xc.x, ee, acc[cI][4]);        \
                acc[cI][5] = ffma2(xc.y, ee, acc[cI][5]);        \
                acc[cI][6] = ffma2(xd.x, ee, acc[cI][6]);        \
                acc[cI][7] = ffma2(xd.y, ee, acc[cI][7]); }
                MMA16(0, e0.x) MMA16(1, e0.y) MMA16(2, e0.z) MMA16(3, e0.w)
                MMA16(4, e1.x) MMA16(5, e1.y) MMA16(6, e1.z) MMA16(7, e1.w)
#undef MMA16
            }
        }

        // chunk epilogue: d = fl(fl(a+b) - fl(2c)); keep running best (key|idx)
        #pragma unroll
        for (int c = 0; c < 8; ++c) {
            int cg = cch * BN + c0 + c;
            float b2 = g_bsq[cg];
            #pragma unroll
            for (int p = 0; p < 8; ++p) {
                float2 v = unpack2(acc[c][p]);
                float t0 = __fadd_rn(ar[2 * p],     b2);
                float t1 = __fadd_rn(ar[2 * p + 1], b2);
                float s0 = __fsub_rn(t0, __fmul_rn(2.0f, v.x));
                float s1 = __fsub_rn(t1, __fmul_rn(2.0f, v.y));
                unsigned long long p0 = ((unsigned long long)okey(s0) << 32) | (unsigned)cg;
                unsigned long long p1 = ((unsigned long long)okey(s1) << 32) | (unsigned)cg;
                best[2 * p]     = umin64(best[2 * p], p0);
                best[2 * p + 1] = umin64(best[2 * p + 1], p1);
            }
        }
    }

    // ---- cross-thread argmin reduction (reuse es region: 64 KB available) ----
    __syncthreads();
    unsigned long long* red = (unsigned long long*)es;          // [BM][32] = 32 KB
    int*    sidx = (int*)((char*)es + BM * 32 * 8);             // +512 B
    double* dred = (double*)((char*)sidx + 1024);               // +2 KB

    #pragma unroll
    for (int r = 0; r < 16; ++r) red[(r0 + r) * 32 + tx] = best[r];
    __syncthreads();
    if (tid < BM) {
        unsigned long long b = red[tid * 32];
        #pragma unroll
        for (int j = 1; j < 32; ++j) b = umin64(b, red[tid * 32 + j]);
        int idx = (int)(b & 0xFFFFFFFFULL);
        sidx[tid] = idx;
        atomicAdd(&g_counts[idx], 1);
    }
    __syncthreads();

    // ---- fused straight-through output + MSE accumulation (coalesced) ----
    double sq = 0.0;
    float* og = out + (size_t)m0 * DIM;
    for (int i = tid; i < BM * DIM; i += NTHR) {
        int row = i >> 8;                     // DIM == 256
        float e = cb[(size_t)sidx[row] * DIM + (i & 255)];
        float xv = xg[i];
        float df = __fsub_rn(e, xv);          // fl(q - x)
        og[i] = __fadd_rn(xv, df);            // fl(x + fl(q - x))
        float s2 = __fmul_rn(df, df);
        sq += (double)s2;
    }
    dred[tid] = sq;
    __syncthreads();
    for (int s = NTHR / 2; s > 0; s >>= 1) {
        if (tid < s) dred[tid] += dred[tid + s];
        __syncthreads();
    }
    if (tid == 0) atomicAdd(&g_sqsum, dred[0]);
}

// ---------------- finalize: loss + perplexity (fp32 combine like reference) ----------------
__global__ void vq_final_kernel(float* __restrict__ out, long long out_size) {
    __shared__ float terms[NCODES];
    int t = threadIdx.x;
    float p = __fdiv_rn((float)g_counts[t], (float)NROWS);
    terms[t] = __fmul_rn(p, logf(__fadd_rn(p, 1e-10f)));
    __syncthreads();
    if (t == 0 && out_size >= (long long)QELEMS + 2) {
        float s = 0.f;
        for (int k = 0; k < NCODES; ++k) s = __fadd_rn(s, terms[k]);
        float m = (float)(g_sqsum / (double)QELEMS);
        out[QELEMS]     = __fadd_rn(m, __fmul_rn(0.25f, m));   // m + 0.25*m
        out[QELEMS + 1] = expf(-s);
    }
}

extern "C" void kernel_launch(void* const* d_in, const int* in_sizes, int n_in,
                              void* d_out, int out_size) {
    const float* x  = (const float*)d_in[0];   // inputs  [8,32,32,32,256]
    const float* cb = (const float*)d_in[1];   // codebook [1024,256]
    float* out = (float*)d_out;

    const int smem_bytes = (DIM * BM + BD * BN + BM) * 4;   // 197120
    cudaFuncSetAttribute(vq_main_kernel,
                         cudaFuncAttributeMaxDynamicSharedMemorySize, smem_bytes);

    vq_init_kernel<<<NCODES, 64>>>(cb);
    vq_main_kernel<<<NROWS / BM, NTHR, smem_bytes>>>(x, cb, out);
    vq_final_kernel<<<1, NCODES>>>(out, (long long)out_size);
}

// round 7
// speedup vs baseline: 1.0997x; 1.0156x over previous
#include <cuda_runtime.h>
#include <cstdint>
#include <math.h>

// VectorQuantizer: N=262144 rows, D=256, K=1024 codes.
// out = [quantized_st (67108864 f32), loss, perplexity]
// Bit-exact replication of XLA:CPU reference arithmetic (validated R2):
//   a[n] = sequential fadd of fl(x_i^2), i ascending
//   b[k] = sequential fadd of fl(e_i^2), i ascending
//   c[n,k] = chained fp32 fma over k ascending, single accumulator
//   d = fl(fl(a+b) - fl(2c)); argmin, lowest-index tie-break
//   out = fl(x + fl(q - x))

#define NROWS   262144
#define DIM     256
#define NCODES  1024
#define BM      128             // rows per CTA
#define BN      128             // codes per chunk
#define BD      64              // dims per smem stage
#define NTHR    512
#define NCHUNK  (NCODES / BN)   // 8
#define NDCH    (DIM / BD)      // 4
#define NSTAGE  (NCHUNK * NDCH) // 32
#define QELEMS  67108864

__device__ float  g_bsq[NCODES];
__device__ int    g_counts[NCODES];
__device__ double g_sqsum;

static __device__ __forceinline__ unsigned long long ffma2(unsigned long long a,
                                                           unsigned long long b,
                                                           unsigned long long c) {
    unsigned long long d;
    asm("fma.rn.f32x2 %0, %1, %2, %3;" : "=l"(d) : "l"(a), "l"(b), "l"(c));
    return d;
}
static __device__ __forceinline__ unsigned long long bcast2(float v) {
    unsigned long long r;
    asm("mov.b64 %0, {%1, %1};" : "=l"(r) : "f"(v));
    return r;
}
static __device__ __forceinline__ float2 unpack2(unsigned long long v) {
    float2 f;
    asm("mov.b64 {%0, %1}, %2;" : "=f"(f.x), "=f"(f.y) : "l"(v));
    return f;
}
// monotone float -> uint key (handles negatives); equal bits preserve ties
static __device__ __forceinline__ unsigned int okey(float s) {
    unsigned int b = __float_as_uint(s);
    return (b & 0x80000000u) ? ~b : (b | 0x80000000u);
}
static __device__ __forceinline__ unsigned long long umin64(unsigned long long a,
                                                            unsigned long long b) {
    return a < b ? a : b;
}

// ---------------- init: one CTA per code; cooperative load, exact chain ----------------
__global__ void vq_init_kernel(const float* __restrict__ cb) {
    __shared__ float row[DIM];
    int k = blockIdx.x;
    int t = threadIdx.x;                 // 64 threads
    const float4* src = (const float4*)(cb + (size_t)k * DIM);
    float4 v = src[t];
    row[t * 4 + 0] = v.x; row[t * 4 + 1] = v.y;
    row[t * 4 + 2] = v.z; row[t * 4 + 3] = v.w;
    __syncthreads();
    if (t == 0) {
        float s = 0.f;
        #pragma unroll 8
        for (int j = 0; j < DIM; ++j) {
            float w = row[j];
            s = __fadd_rn(s, __fmul_rn(w, w));   // strict sequential, j ascending
        }
        g_bsq[k] = s;
        g_counts[k] = 0;
        if (k == 0) g_sqsum = 0.0;
    }
}

// ---------------- main: pipelined GEMM + rounded scoring + argmin + gather + MSE ----------------
__global__ __launch_bounds__(NTHR, 1)
void vq_main_kernel(const float* __restrict__ x, const float* __restrict__ cb,
                    float* __restrict__ out) {
    extern __shared__ float smem[];
    float* xs = smem;                           // [DIM][BM]  transposed x, 128 KB
    float* es = smem + DIM * BM;                // 2 x [BD][BN] double buffer, 64 KB
    float* sa = smem + DIM * BM + 2 * BD * BN;  // [BM] row sumsq

    const int tid = threadIdx.x;
    const int tx = tid & 31;                    // 32 code groups * 4 codes = 128
    const int ty = tid >> 5;                    // 16 row groups * 8 rows = 128
    const int r0 = ty * 8;
    const int c0 = tx * 4;
    const int m0 = blockIdx.x * BM;
    const float* xg = x + (size_t)m0 * DIM;

    // staging role of this thread (fixed): one code row, 4 dim-groups
    const int scode = tid & (BN - 1);           // 0..127
    const int sdgb  = tid >> 7;                 // 0..3

    // Load x tile transposed: xs[d][row]
    for (int i = tid; i < BM * (DIM / 4); i += NTHR) {
        int row = i & (BM - 1);
        int dg  = i >> 7;                       // 0..63
        float4 v = *(const float4*)(xg + (size_t)row * DIM + dg * 4);
        xs[(dg * 4 + 0) * BM + row] = v.x;
        xs[(dg * 4 + 1) * BM + row] = v.y;
        xs[(dg * 4 + 2) * BM + row] = v.z;
        xs[(dg * 4 + 3) * BM + row] = v.w;
    }

    // Prefetch stage 0 (cch=0, dch=0) into registers
    float4 pf[4];
    #pragma unroll
    for (int j = 0; j < 4; ++j) {
        int dg = sdgb + 4 * j;                  // 0..15
        pf[j] = *(const float4*)(cb + (size_t)scode * DIM + dg * 4);
    }

    __syncthreads();   // xs ready

    // STS stage 0 into buffer 0
    #pragma unroll
    for (int j = 0; j < 4; ++j) {
        int dg = sdgb + 4 * j;
        es[(dg * 4 + 0) * BN + scode] = pf[j].x;
        es[(dg * 4 + 1) * BN + scode] = pf[j].y;
        es[(dg * 4 + 2) * BN + scode] = pf[j].z;
        es[(dg * 4 + 3) * BN + scode] = pf[j].w;
    }

    // a[n]: strict sequential sum of fl(x^2), d ascending
    if (tid < BM) {
        float aa = 0.f;
        for (int d = 0; d < DIM; ++d) {
            float v = xs[d * BM + tid];
            aa = __fadd_rn(aa, __fmul_rn(v, v));
        }
        sa[tid] = aa;
    }
    __syncthreads();   // stage 0 + sa ready

    float ar[8];
    #pragma unroll
    for (int r = 0; r < 8; ++r) ar[r] = sa[r0 + r];

    unsigned long long best[8];
    #pragma unroll
    for (int r = 0; r < 8; ++r) best[r] = 0xFFFFFFFFFFFFFFFFULL;

    unsigned long long acc[4][4];               // [code][rowpair] chained fma, k ascending

    for (int st = 0; st < NSTAGE; ++st) {
        const int cch = st >> 2;
        const int dch = st & 3;

        // Prefetch next stage while computing this one
        if (st + 1 < NSTAGE) {
            const int nc = (st + 1) >> 2;
            const int nd = (st + 1) & 3;
            const float* src = cb + (size_t)(nc * BN + scode) * DIM + nd * BD;
            #pragma unroll
            for (int j = 0; j < 4; ++j) {
                int dg = sdgb + 4 * j;
                pf[j] = *(const float4*)(src + dg * 4);
            }
        }

        if (dch == 0) {
            #pragma unroll
            for (int c = 0; c < 4; ++c)
                #pragma unroll
                for (int p = 0; p < 4; ++p) acc[c][p] = 0ULL;
        }

        const float* xb = xs + dch * BD * BM + r0;
        const float* eb = es + (st & 1) * (BD * BN) + c0;
        #pragma unroll 8
        for (int dl = 0; dl < BD; ++dl) {       // k ascending within stage
            ulonglong2 xa = *(const ulonglong2*)(xb + dl * BM);       // rows +0..3
            ulonglong2 xc = *(const ulonglong2*)(xb + dl * BM + 4);   // rows +4..7
            float4 e = *(const float4*)(eb + dl * BN);
#define MMA4(cI, ev) { unsigned long long ee = bcast2(ev);       \
            acc[cI][0] = ffma2(xa.x, ee, acc[cI][0]);            \
            acc[cI][1] = ffma2(xa.y, ee, acc[cI][1]);            \
            acc[cI][2] = ffma2(xc.x, ee, acc[cI][2]);            \
            acc[cI][3] = ffma2(xc.y, ee, acc[cI][3]); }
            MMA4(0, e.x) MMA4(1, e.y) MMA4(2, e.z) MMA4(3, e.w)
#undef MMA4
        }

        if (dch == 3) {
            // chunk epilogue: d = fl(fl(a+b) - fl(2c)); keep running best
            #pragma unroll
            for (int c = 0; c < 4; ++c) {
                int cg = cch * BN + c0 + c;
                float b2 = g_bsq[cg];
                #pragma unroll
                for (int p = 0; p < 4; ++p) {
                    float2 v = unpack2(acc[c][p]);
                    float t0 = __fadd_rn(ar[2 * p],     b2);
                    float t1 = __fadd_rn(ar[2 * p + 1], b2);
                    float s0 = __fsub_rn(t0, __fmul_rn(2.0f, v.x));
                    float s1 = __fsub_rn(t1, __fmul_rn(2.0f, v.y));
                    unsigned long long p0 = ((unsigned long long)okey(s0) << 32) | (unsigned)cg;
                    unsigned long long p1 = ((unsigned long long)okey(s1) << 32) | (unsigned)cg;
                    best[2 * p]     = umin64(best[2 * p], p0);
                    best[2 * p + 1] = umin64(best[2 * p + 1], p1);
                }
            }
        }

        // STS next stage into the idle buffer (no one reads it this stage)
        if (st + 1 < NSTAGE) {
            float* dst = es + ((st + 1) & 1) * (BD * BN);
            #pragma unroll
            for (int j = 0; j < 4; ++j) {
                int dg = sdgb + 4 * j;
                dst[(dg * 4 + 0) * BN + scode] = pf[j].x;
                dst[(dg * 4 + 1) * BN + scode] = pf[j].y;
                dst[(dg * 4 + 2) * BN + scode] = pf[j].z;
                dst[(dg * 4 + 3) * BN + scode] = pf[j].w;
            }
            __syncthreads();                     // next buffer ready for all
        }
    }

    // ---- cross-thread argmin reduction (reuse es region: 64 KB scratch) ----
    __syncthreads();
    unsigned long long* red = (unsigned long long*)es;          // [BM][32] = 32 KB
    int*    sidx = (int*)((char*)es + BM * 32 * 8);             // +512 B
    double* dred = (double*)((char*)sidx + 2048);               // +4 KB

    #pragma unroll
    for (int r = 0; r < 8; ++r) red[(r0 + r) * 32 + tx] = best[r];
    __syncthreads();
    if (tid < BM) {
        unsigned long long b = red[tid * 32];
        #pragma unroll
        for (int j = 1; j < 32; ++j) b = umin64(b, red[tid * 32 + j]);
        int idx = (int)(b & 0xFFFFFFFFULL);
        sidx[tid] = idx;
        atomicAdd(&g_counts[idx], 1);
    }
    __syncthreads();

    // ---- fused straight-through output + MSE accumulation (coalesced) ----
    double sq = 0.0;
    float* og = out + (size_t)m0 * DIM;
    for (int i = tid; i < BM * DIM; i += NTHR) {
        int row = i >> 8;                        // DIM == 256
        float e = cb[(size_t)sidx[row] * DIM + (i & 255)];
        float xv = xg[i];
        float df = __fsub_rn(e, xv);             // fl(q - x)
        og[i] = __fadd_rn(xv, df);               // fl(x + fl(q - x))
        float s2 = __fmul_rn(df, df);
        sq += (double)s2;
    }
    dred[tid] = sq;
    __syncthreads();
    for (int s = NTHR / 2; s > 0; s >>= 1) {
        if (tid < s) dred[tid] += dred[tid + s];
        __syncthreads();
    }
    if (tid == 0) atomicAdd(&g_sqsum, dred[0]);
}

// ---------------- finalize: loss + perplexity (fp32 combine like reference) ----------------
__global__ void vq_final_kernel(float* __restrict__ out, long long out_size) {
    __shared__ float terms[NCODES];
    int t = threadIdx.x;
    float p = __fdiv_rn((float)g_counts[t], (float)NROWS);
    terms[t] = __fmul_rn(p, logf(__fadd_rn(p, 1e-10f)));
    __syncthreads();
    if (t == 0 && out_size >= (long long)QELEMS + 2) {
        float s = 0.f;
        for (int k = 0; k < NCODES; ++k) s = __fadd_rn(s, terms[k]);
        float m = (float)(g_sqsum / (double)QELEMS);
        out[QELEMS]     = __fadd_rn(m, __fmul_rn(0.25f, m));   // m + 0.25*m
        out[QELEMS + 1] = expf(-s);
    }
}

extern "C" void kernel_launch(void* const* d_in, const int* in_sizes, int n_in,
                              void* d_out, int out_size) {
    const float* x  = (const float*)d_in[0];   // inputs  [8,32,32,32,256]
    const float* cb = (const float*)d_in[1];   // codebook [1024,256]
    float* out = (float*)d_out;

    const int smem_bytes = (DIM * BM + 2 * BD * BN + BM) * 4;   // 197120
    cudaFuncSetAttribute(vq_main_kernel,
                         cudaFuncAttributeMaxDynamicSharedMemorySize, smem_bytes);

    vq_init_kernel<<<NCODES, 64>>>(cb);
    vq_main_kernel<<<NROWS / BM, NTHR, smem_bytes>>>(x, cb, out);
    vq_final_kernel<<<1, NCODES>>>(out, (long long)out_size);
}